// round 1
// baseline (speedup 1.0000x reference)
#include <cuda_runtime.h>
#include <cuda_bf16.h>
#include <math.h>

// Problem constants
#define BB   4
#define CINE 256
#define CIN  1024
#define CO   256
#define HW   16384        // H*W = 128*128
#define CQ   32
#define NPOS 16384.0f

// Scratch (device globals -- no runtime allocation allowed)
__device__ float g_x[(size_t)BB * CO * HW];   // conv out, then feat (in-place BN+ReLU)
__device__ float g_v[(size_t)BB * CO * HW];   // V
__device__ float g_q[BB * CQ * HW];           // Q then Qn
__device__ float g_k[BB * CQ * HW];           // K then Kn
__device__ float g_mean[CO];
__device__ float g_invstd[CO];
__device__ float g_ksum[BB * CQ];
__device__ float g_vsum[BB * CO];
__device__ float g_matrix[BB * CQ * CO];

__device__ __forceinline__ float fixnum(float r) {
    if (isnan(r)) return 0.0f;
    if (isinf(r)) return r > 0.0f ? 1.0f : -1.0f;
    return r;
}

// ---------------------------------------------------------------------------
// zero accumulators used with atomics
__global__ void zero_kernel() {
    int tid = blockIdx.x * blockDim.x + threadIdx.x;
    int total = BB * CQ + BB * CQ * CO;  // g_ksum + g_matrix
    for (int i = tid; i < total; i += gridDim.x * blockDim.x) {
        if (i < BB * CQ) g_ksum[i] = 0.0f;
        else g_matrix[i - BB * CQ] = 0.0f;
    }
}

// ---------------------------------------------------------------------------
// 1x1 conv GEMM: g_x[b,m,n] = sum_c w[m,c] * fcat[b,c,n]
// 128x128 tile, BK=8, 256 threads, 8x8 per-thread microtile.
__global__ __launch_bounds__(256) void conv_gemm(
    const float* __restrict__ s5, const float* __restrict__ s4,
    const float* __restrict__ s3, const float* __restrict__ s2,
    const float* __restrict__ w)
{
    const int b  = blockIdx.z;
    const int m0 = blockIdx.y * 128;
    const int n0 = blockIdx.x * 128;

    __shared__ float sA[8][128];
    __shared__ float sB[8][128];

    const int t  = threadIdx.x;
    const int tx = t % 16;
    const int ty = t / 16;

    // A loader: thread -> (row = t/2, kq = (t%2)*4)
    const int arow = t >> 1;
    const int akq  = (t & 1) * 4;
    // B loader: thread -> (kk = t/32, nq = (t%32)*4)
    const int bkk = t >> 5;
    const int bnq = (t & 31) * 4;

    float acc[8][8];
#pragma unroll
    for (int i = 0; i < 8; i++)
#pragma unroll
        for (int j = 0; j < 8; j++) acc[i][j] = 0.0f;

    for (int k0 = 0; k0 < CIN; k0 += 8) {
        // load A (w_conv), transpose to [k][m]
        float4 a4 = *(const float4*)(w + (size_t)(m0 + arow) * CIN + k0 + akq);
        sA[akq + 0][arow] = a4.x;
        sA[akq + 1][arow] = a4.y;
        sA[akq + 2][arow] = a4.z;
        sA[akq + 3][arow] = a4.w;

        // load B (concatenated inputs)
        int ch = k0 + bkk;  // 0..1023, constant source per 8-row tile row
        const float* src = (ch < 512) ? (ch < 256 ? s5 : s4)
                                      : (ch < 768 ? s3 : s2);
        float4 b4 = *(const float4*)(src + (size_t)(b * CINE + (ch & 255)) * HW + n0 + bnq);
        *(float4*)&sB[bkk][bnq] = b4;

        __syncthreads();

#pragma unroll
        for (int kk = 0; kk < 8; kk++) {
            float ra[8], rb[8];
#pragma unroll
            for (int i = 0; i < 8; i++) ra[i] = sA[kk][ty * 8 + i];
#pragma unroll
            for (int j = 0; j < 8; j++) rb[j] = sB[kk][tx * 8 + j];
#pragma unroll
            for (int i = 0; i < 8; i++)
#pragma unroll
                for (int j = 0; j < 8; j++)
                    acc[i][j] += ra[i] * rb[j];
        }
        __syncthreads();
    }

#pragma unroll
    for (int i = 0; i < 8; i++) {
        int m = m0 + ty * 8 + i;
        float* dst = g_x + (size_t)(b * CO + m) * HW + n0 + tx * 8;
        *(float4*)(dst + 0) = make_float4(acc[i][0], acc[i][1], acc[i][2], acc[i][3]);
        *(float4*)(dst + 4) = make_float4(acc[i][4], acc[i][5], acc[i][6], acc[i][7]);
    }
}

// ---------------------------------------------------------------------------
// BN statistics: one block per channel, reduce over B*HW = 65536 elements
__global__ __launch_bounds__(512) void bn_stats() {
    const int co = blockIdx.x;
    const int tid = threadIdx.x;
    float s = 0.0f, ss = 0.0f;
    for (int b = 0; b < BB; b++) {
        const float* p = g_x + (size_t)(b * CO + co) * HW;
        for (int i = tid; i < HW; i += 512) {
            float v = p[i];
            s += v;
            ss += v * v;
        }
    }
    __shared__ float rs[512], rss[512];
    rs[tid] = s; rss[tid] = ss;
    __syncthreads();
    for (int off = 256; off > 0; off >>= 1) {
        if (tid < off) { rs[tid] += rs[tid + off]; rss[tid] += rss[tid + off]; }
        __syncthreads();
    }
    if (tid == 0) {
        const float cnt = (float)(BB * HW);
        float mean = rs[0] / cnt;
        float var  = rss[0] / cnt - mean * mean;   // biased, matches torch BN
        g_mean[co]   = mean;
        g_invstd[co] = rsqrtf(var + 1e-5f);
    }
}

// ---------------------------------------------------------------------------
// BN affine + ReLU in place on g_x (vectorized float4)
__global__ __launch_bounds__(256) void bn_relu(
    const float* __restrict__ bn_gamma, const float* __restrict__ bn_beta)
{
    int idx4 = blockIdx.x * blockDim.x + threadIdx.x;  // total = BB*CO*HW/4 = 16M/4
    if (idx4 >= (BB * CO * HW) / 4) return;
    int c = (idx4 >> 12) & (CO - 1);                   // HW/4 = 4096 float4 per (b,c) row
    float scale = g_invstd[c] * bn_gamma[c];
    float shift = bn_beta[c] - g_mean[c] * scale;
    float4 v = ((float4*)g_x)[idx4];
    v.x = fmaxf(v.x * scale + shift, 0.0f);
    v.y = fmaxf(v.y * scale + shift, 0.0f);
    v.z = fmaxf(v.z * scale + shift, 0.0f);
    v.w = fmaxf(v.w * scale + shift, 0.0f);
    ((float4*)g_x)[idx4] = v;
}

// ---------------------------------------------------------------------------
// Fused QKV GEMM: rows 0..31 = Q, 32..63 = K, 64..319 = V.  K-dim = 256 (feat channels)
__global__ __launch_bounds__(256) void qkv_gemm(
    const float* __restrict__ wq, const float* __restrict__ bq,
    const float* __restrict__ wk, const float* __restrict__ bk,
    const float* __restrict__ wv, const float* __restrict__ bv)
{
    const int b  = blockIdx.z;
    const int m0 = blockIdx.y * 128;     // 0,128,256 (rows 256..383 partially valid)
    const int n0 = blockIdx.x * 128;

    __shared__ float sA[8][128];
    __shared__ float sB[8][128];

    const int t  = threadIdx.x;
    const int tx = t % 16;
    const int ty = t / 16;
    const int arow = t >> 1;
    const int akq  = (t & 1) * 4;
    const int bkk = t >> 5;
    const int bnq = (t & 31) * 4;

    float acc[8][8];
#pragma unroll
    for (int i = 0; i < 8; i++)
#pragma unroll
        for (int j = 0; j < 8; j++) acc[i][j] = 0.0f;

    for (int k0 = 0; k0 < CO; k0 += 8) {
        int m = m0 + arow;
        float4 a4 = make_float4(0.f, 0.f, 0.f, 0.f);
        if (m < 320) {
            const float* wrow;
            if (m < 32)       wrow = wq + (size_t)m * CO;
            else if (m < 64)  wrow = wk + (size_t)(m - 32) * CO;
            else              wrow = wv + (size_t)(m - 64) * CO;
            a4 = *(const float4*)(wrow + k0 + akq);
        }
        sA[akq + 0][arow] = a4.x;
        sA[akq + 1][arow] = a4.y;
        sA[akq + 2][arow] = a4.z;
        sA[akq + 3][arow] = a4.w;

        int ch = k0 + bkk;
        float4 b4 = *(const float4*)(g_x + (size_t)(b * CO + ch) * HW + n0 + bnq);
        *(float4*)&sB[bkk][bnq] = b4;

        __syncthreads();
#pragma unroll
        for (int kk = 0; kk < 8; kk++) {
            float ra[8], rb[8];
#pragma unroll
            for (int i = 0; i < 8; i++) ra[i] = sA[kk][ty * 8 + i];
#pragma unroll
            for (int j = 0; j < 8; j++) rb[j] = sB[kk][tx * 8 + j];
#pragma unroll
            for (int i = 0; i < 8; i++)
#pragma unroll
                for (int j = 0; j < 8; j++)
                    acc[i][j] += ra[i] * rb[j];
        }
        __syncthreads();
    }

#pragma unroll
    for (int i = 0; i < 8; i++) {
        int m = m0 + ty * 8 + i;
        if (m >= 320) continue;
        float bias;
        float* dst;
        if (m < 32)      { bias = bq[m];      dst = g_q + (size_t)(b * CQ + m) * HW; }
        else if (m < 64) { bias = bk[m - 32]; dst = g_k + (size_t)(b * CQ + m - 32) * HW; }
        else             { bias = bv[m - 64]; dst = g_v + (size_t)(b * CO + m - 64) * HW; }
        float* p = dst + n0 + tx * 8;
        *(float4*)(p + 0) = make_float4(acc[i][0] + bias, acc[i][1] + bias,
                                        acc[i][2] + bias, acc[i][3] + bias);
        *(float4*)(p + 4) = make_float4(acc[i][4] + bias, acc[i][5] + bias,
                                        acc[i][6] + bias, acc[i][7] + bias);
    }
}

// ---------------------------------------------------------------------------
// L2-normalize Q and K over the 32-channel dim (per position), accumulate Ksum
__global__ __launch_bounds__(256) void normalize_qk() {
    const int b = blockIdx.y;
    const int n = blockIdx.x * 256 + threadIdx.x;
    const int lane = threadIdx.x & 31;

    // Q
    {
        float q[CQ];
        float s = 0.0f;
#pragma unroll
        for (int c = 0; c < CQ; c++) {
            q[c] = g_q[(size_t)(b * CQ + c) * HW + n];
            s += q[c] * q[c];
        }
        float sc = 1.0f / fmaxf(sqrtf(s), 1e-6f);
#pragma unroll
        for (int c = 0; c < CQ; c++)
            g_q[(size_t)(b * CQ + c) * HW + n] = q[c] * sc;
    }
    // K (+ Ksum)
    {
        float k[CQ];
        float s = 0.0f;
#pragma unroll
        for (int c = 0; c < CQ; c++) {
            k[c] = g_k[(size_t)(b * CQ + c) * HW + n];
            s += k[c] * k[c];
        }
        float sc = 1.0f / fmaxf(sqrtf(s), 1e-6f);
#pragma unroll
        for (int c = 0; c < CQ; c++) {
            float v = k[c] * sc;
            g_k[(size_t)(b * CQ + c) * HW + n] = v;
            float r = v;
#pragma unroll
            for (int off = 16; off > 0; off >>= 1)
                r += __shfl_down_sync(0xffffffffu, r, off);
            if (lane == 0) atomicAdd(&g_ksum[b * CQ + c], r);
        }
    }
}

// ---------------------------------------------------------------------------
// Vsum[b,c] = sum_n V[b,c,n]
__global__ __launch_bounds__(256) void vsum_kernel() {
    const int c = blockIdx.x;
    const int b = blockIdx.y;
    const int tid = threadIdx.x;
    const float* p = g_v + (size_t)(b * CO + c) * HW;
    float s = 0.0f;
    for (int i = tid; i < HW; i += 256) s += p[i];
    __shared__ float rs[256];
    rs[tid] = s;
    __syncthreads();
    for (int off = 128; off > 0; off >>= 1) {
        if (tid < off) rs[tid] += rs[tid + off];
        __syncthreads();
    }
    if (tid == 0) g_vsum[b * CO + c] = rs[0];
}

// ---------------------------------------------------------------------------
// matrix[b,q,c] = sum_n Kn[b,q,n] * V[b,c,n]  (split-K over n, atomic reduce)
__global__ __launch_bounds__(256) void matrix_kernel() {
    const int b   = blockIdx.z;
    const int c0  = blockIdx.y * 64;
    const int nb0 = blockIdx.x * 512;   // 32 splits of 512

    __shared__ float sK[CQ][65];
    __shared__ float sV[64][65];

    const int t  = threadIdx.x;
    const int c  = t & 63;
    const int qg = t >> 6;   // 0..3, each handles 8 q rows

    float acc[8];
#pragma unroll
    for (int i = 0; i < 8; i++) acc[i] = 0.0f;

    for (int nb = nb0; nb < nb0 + 512; nb += 64) {
#pragma unroll
        for (int i = 0; i < 8; i++) {            // 2048 K floats
            int idx = t + i * 256;
            int q = idx >> 6, j = idx & 63;
            sK[q][j] = g_k[(size_t)(b * CQ + q) * HW + nb + j];
        }
#pragma unroll
        for (int i = 0; i < 16; i++) {           // 4096 V floats
            int idx = t + i * 256;
            int cc = idx >> 6, j = idx & 63;
            sV[cc][j] = g_v[(size_t)(b * CO + c0 + cc) * HW + nb + j];
        }
        __syncthreads();
#pragma unroll 8
        for (int j = 0; j < 64; j++) {
            float vv = sV[c][j];
#pragma unroll
            for (int i = 0; i < 8; i++)
                acc[i] += sK[qg * 8 + i][j] * vv;
        }
        __syncthreads();
    }
#pragma unroll
    for (int i = 0; i < 8; i++)
        atomicAdd(&g_matrix[(size_t)(b * CQ + qg * 8 + i) * CO + c0 + c], acc[i]);
}

// ---------------------------------------------------------------------------
// Final: out = nan_to_num(gamma * (Vsum + Qn^T matrix) * tailor) + feat
__global__ __launch_bounds__(128) void final_kernel(
    const float* __restrict__ gamma_p, float* __restrict__ out)
{
    const int b = blockIdx.y;
    const int n = blockIdx.x * 128 + threadIdx.x;
    const int tid = threadIdx.x;

    __shared__ float sM[CQ][CO];   // 32 KB
    __shared__ float sVs[CO];
    __shared__ float sKs[CQ];

    // load matrix / vsum / ksum
#pragma unroll
    for (int i = 0; i < 64; i++) {
        int idx = tid + i * 128;
        ((float*)sM)[idx] = g_matrix[(size_t)b * CQ * CO + idx];
    }
    sVs[tid]       = g_vsum[b * CO + tid];
    sVs[tid + 128] = g_vsum[b * CO + tid + 128];
    if (tid < CQ) sKs[tid] = g_ksum[b * CQ + tid];
    __syncthreads();

    float qn[CQ];
    float e = 0.0f;
#pragma unroll
    for (int q = 0; q < CQ; q++) {
        qn[q] = g_q[(size_t)(b * CQ + q) * HW + n];
        e += qn[q] * sKs[q];
    }
    const float tailor = 1.0f / fmaxf(NPOS + e, 1e-6f);
    const float gm = *gamma_p;

    for (int c0 = 0; c0 < CO; c0 += 4) {
        float4 a = *(const float4*)&sVs[c0];
#pragma unroll
        for (int q = 0; q < CQ; q++) {
            float4 m4 = *(const float4*)&sM[q][c0];
            a.x += qn[q] * m4.x;
            a.y += qn[q] * m4.y;
            a.z += qn[q] * m4.z;
            a.w += qn[q] * m4.w;
        }
        float r0 = fixnum(gm * a.x * tailor);
        float r1 = fixnum(gm * a.y * tailor);
        float r2 = fixnum(gm * a.z * tailor);
        float r3 = fixnum(gm * a.w * tailor);
        size_t base = (size_t)(b * CO + c0) * HW + n;
        out[base + 0 * HW] = r0 + g_x[base + 0 * HW];
        out[base + 1 * HW] = r1 + g_x[base + 1 * HW];
        out[base + 2 * HW] = r2 + g_x[base + 2 * HW];
        out[base + 3 * HW] = r3 + g_x[base + 3 * HW];
    }
}

// ---------------------------------------------------------------------------
extern "C" void kernel_launch(void* const* d_in, const int* in_sizes, int n_in,
                              void* d_out, int out_size)
{
    const float* s5 = (const float*)d_in[0];
    const float* s4 = (const float*)d_in[1];
    const float* s3 = (const float*)d_in[2];
    const float* s2 = (const float*)d_in[3];
    const float* w_conv   = (const float*)d_in[4];
    const float* bn_gamma = (const float*)d_in[5];
    const float* bn_beta  = (const float*)d_in[6];
    const float* wq = (const float*)d_in[7];
    const float* bq = (const float*)d_in[8];
    const float* wk = (const float*)d_in[9];
    const float* bk = (const float*)d_in[10];
    const float* wv = (const float*)d_in[11];
    const float* bv = (const float*)d_in[12];
    const float* gamma = (const float*)d_in[13];
    float* out = (float*)d_out;

    zero_kernel<<<64, 256>>>();
    conv_gemm<<<dim3(HW / 128, CO / 128, BB), 256>>>(s5, s4, s3, s2, w_conv);
    bn_stats<<<CO, 512>>>();
    bn_relu<<<(BB * CO * HW / 4 + 255) / 256, 256>>>(bn_gamma, bn_beta);
    qkv_gemm<<<dim3(HW / 128, 3, BB), 256>>>(wq, bq, wk, bk, wv, bv);
    normalize_qk<<<dim3(HW / 256, BB), 256>>>();
    vsum_kernel<<<dim3(CO, BB), 256>>>();
    matrix_kernel<<<dim3(32, CO / 64, BB), 256>>>();
    final_kernel<<<dim3(HW / 128, BB), 128>>>(gamma, out);
}